// round 11
// baseline (speedup 1.0000x reference)
#include <cuda_runtime.h>
#include <cuda_bf16.h>
#include <cstdint>

// Att_mask R11: R10 skeleton (register-resident HMMA pipeline, 24 warps/SM) +
//  * paired-reciprocal tanh (1 rcp per 2 tanh) -> MUFU -20%
//  * scl2 folded into Q fragments pre-split (removes 32 score muls)
//  * prefetch.global.L2 of next batch's x (consecutive batches per warp)
//  * ITERS 8 / NCTAS 1024 -> 2.3 waves

typedef unsigned long long ull;

#define THREADS 256
#define WPB     8
#define NCTAS   1024
#define ITERS   8            // 1024 * 8 warps * 8 = 65536 batches

#define SM_WHI   0           // 96 rows x 128B bf16, chunk-swizzled
#define SM_WLO   12288
#define SM_WARP0 24576
#define PW_BYTES 6144        // per-warp: xhi 3072 | xlo 3072
#define SMEM_BYTES (SM_WARP0 + WPB * PW_BYTES + 128)

#define XROW_B   48          // x bf16 tile row stride (conflict-free LDSM.trans)
#define TANH_K   2.8853900817779268f   // 2*log2(e)

// ---------------- packed f32x2 helpers ----------------
__device__ __forceinline__ ull pack2(float lo, float hi) {
    ull r; asm("mov.b64 %0, {%1, %2};" : "=l"(r) : "f"(lo), "f"(hi)); return r;
}
__device__ __forceinline__ void unpack2(ull v, float& lo, float& hi) {
    asm("mov.b64 {%0, %1}, %2;" : "=f"(lo), "=f"(hi) : "l"(v));
}
__device__ __forceinline__ void fma2(ull& d, ull a, ull b) {
    asm("fma.rn.f32x2 %0, %1, %2, %0;" : "+l"(d) : "l"(a), "l"(b));
}
__device__ __forceinline__ ull add2(ull a, ull b) {
    ull r; asm("add.rn.f32x2 %0, %1, %2;" : "=l"(r) : "l"(a), "l"(b)); return r;
}
__device__ __forceinline__ float ex2f(float x) {
    float r; asm("ex2.approx.f32 %0, %1;" : "=f"(r) : "f"(x)); return r;
}
__device__ __forceinline__ float rcpf(float x) {
    float r; asm("rcp.approx.f32 %0, %1;" : "=f"(r) : "f"(x)); return r;
}
// two tanh sharing one MUFU.RCP: tanh(x) = 1 - 2/(exp(2x)+1)
__device__ __forceinline__ void tanh_pair(float& a, float& b) {
    float ea = ex2f(TANH_K * a), eb = ex2f(TANH_K * b);
    float pa = ea + 1.0f, pb = eb + 1.0f;
    float r  = rcpf(pa * pb);
    float ta = r * pb, tb = r * pa;
    a = fmaf(-2.0f, ta, 1.0f);
    b = fmaf(-2.0f, tb, 1.0f);
}

// ---------------- smem / mma helpers ----------------
__device__ __forceinline__ unsigned smem_u32(const void* p) {
    unsigned a;
    asm("{ .reg .u64 t; cvta.to.shared.u64 t, %1; cvt.u32.u64 %0, t; }" : "=r"(a) : "l"(p));
    return a;
}
__device__ __forceinline__ unsigned cvtpack2(float lo, float hi) {
    unsigned r; asm("cvt.rn.bf16x2.f32 %0, %1, %2;" : "=r"(r) : "f"(hi), "f"(lo)); return r;
}
__device__ __forceinline__ void split_pair(float a, float b, unsigned& hi, unsigned& lo) {
    hi = cvtpack2(a, b);
    float ha = __uint_as_float(hi << 16);
    float hb = __uint_as_float(hi & 0xffff0000u);
    lo = cvtpack2(a - ha, b - hb);
}
__device__ __forceinline__ void ldsm_x4(unsigned r[4], unsigned addr) {
    asm volatile("ldmatrix.sync.aligned.m8n8.x4.shared.b16 {%0,%1,%2,%3}, [%4];"
                 : "=r"(r[0]), "=r"(r[1]), "=r"(r[2]), "=r"(r[3]) : "r"(addr));
}
__device__ __forceinline__ void ldsm_x4_t(unsigned r[4], unsigned addr) {
    asm volatile("ldmatrix.sync.aligned.m8n8.x4.trans.shared.b16 {%0,%1,%2,%3}, [%4];"
                 : "=r"(r[0]), "=r"(r[1]), "=r"(r[2]), "=r"(r[3]) : "r"(addr));
}
__device__ __forceinline__ void mma_bf16(float* c, const unsigned* a, const unsigned* b) {
    asm volatile("mma.sync.aligned.m16n8k16.row.col.f32.bf16.bf16.f32 "
                 "{%0,%1,%2,%3}, {%4,%5,%6,%7}, {%8,%9}, {%0,%1,%2,%3};"
                 : "+f"(c[0]), "+f"(c[1]), "+f"(c[2]), "+f"(c[3])
                 : "r"(a[0]), "r"(a[1]), "r"(a[2]), "r"(a[3]), "r"(b[0]), "r"(b[1]));
}
__device__ __forceinline__ void sts_v2(unsigned addr, unsigned a, unsigned b) {
    asm volatile("st.shared.v2.b32 [%0], {%1, %2};" :: "r"(addr), "r"(a), "r"(b));
}

__global__ void __launch_bounds__(THREADS, 3) att_mask_kernel(
    const float* __restrict__ x, const float* __restrict__ L,
    const float* __restrict__ Aq, const float* __restrict__ Ak,
    const float* __restrict__ Av, const float* __restrict__ Ao,
    float* __restrict__ out)
{
    extern __shared__ char smem[];
    const int tid  = threadIdx.x;
    const int warp = tid >> 5;
    const int lane = tid & 31;
    const int g    = lane >> 2;
    const unsigned smem_base = smem_u32(smem);

    // ---- stage W split-bf16, chunk-swizzled [96 rows][128B] (proven) ----
    for (int idx = tid; idx < 6144; idx += THREADS) {
        int row = idx >> 6, d = idx & 63;
        float val = (row < 32) ? Aq[row * 64 + d]
                  : (row < 64) ? Ak[(row - 32) * 64 + d]
                               : Av[(row - 64) * 64 + d];
        __nv_bfloat16 h = __float2bfloat16(val);
        __nv_bfloat16 l = __float2bfloat16(val - __bfloat162float(h));
        int off = row * 128 + (((d >> 3) ^ (row & 7)) << 4) + (d & 7) * 2;
        *(__nv_bfloat16*)(smem + SM_WHI + off) = h;
        *(__nv_bfloat16*)(smem + SM_WLO + off) = l;
    }
    float aoR0 = __ldg(Ao + g);
    float aoR1 = __ldg(Ao + g + 8);
    float aoR2 = __ldg(Ao + g + 16);
    float aoR3 = __ldg(Ao + g + 24);
    __syncthreads();

    const unsigned xhib = smem_base + SM_WARP0 + warp * PW_BYTES;
    const unsigned xlob = xhib + 3072;

    // ldmatrix lane addressing (proven)
    const int lm = lane >> 3;
    const int li = lane & 7;
    const unsigned a_row  = ((lm & 1) << 3) + li;
    const unsigned a_cb   = (unsigned)(lm >> 1);
    const unsigned b_roff = (((lm & 1) << 3) + li) * XROW_B + ((lm >> 1) << 4);

    const int gw = blockIdx.x * WPB + warp;

    for (int it = 0; it < ITERS; ++it) {
        const int b = gw * ITERS + it;    // consecutive batches per warp

        // ---- load x coalesced + L ----
        const float4* xg4 = (const float4*)(x + (size_t)b * 1024);
        float4 xv[8];
        #pragma unroll
        for (int j = 0; j < 8; ++j) xv[j] = xg4[j * 32 + lane];
        float lv = (lane < 16) ? __ldg(L + (size_t)b * 256 + lane) : 0.0f;

        __syncwarp();

        // ---- convert x to bf16 hi/lo tiles [d=64][n=16], rows 48B ----
        #pragma unroll
        for (int j = 0; j < 8; ++j) {
            float4 v = xv[j];
            unsigned h01 = cvtpack2(v.x, v.y);
            unsigned h23 = cvtpack2(v.z, v.w);
            float f0 = __uint_as_float(h01 << 16);
            float f1 = __uint_as_float(h01 & 0xffff0000u);
            float f2 = __uint_as_float(h23 << 16);
            float f3 = __uint_as_float(h23 & 0xffff0000u);
            unsigned l01 = cvtpack2(v.x - f0, v.y - f1);
            unsigned l23 = cvtpack2(v.z - f2, v.w - f3);
            unsigned off = (unsigned)((8 * j + (lane >> 2)) * XROW_B + (lane & 3) * 8);
            sts_v2(xhib + off, h01, h23);
            sts_v2(xlob + off, l01, l23);
        }
        // ---- L2 prefetch of next iteration's x (4KB via lane*128) ----
        if (it + 1 < ITERS) {
            const char* nx = (const char*)(x + (size_t)(b + 1) * 1024);
            asm volatile("prefetch.global.L2 [%0];" :: "l"(nx + lane * 128));
        }
        __syncwarp();

        // ---- projection: 3 terms x (6 mt x 2 nt x 4 kt) mma.sync ----
        float acc[6][8];
        #pragma unroll
        for (int mt = 0; mt < 6; ++mt)
            #pragma unroll
            for (int p = 0; p < 8; ++p) acc[mt][p] = 0.0f;

        #pragma unroll
        for (int kt = 0; kt < 4; ++kt) {
            unsigned bh[4], bl[4];
            unsigned boff = (unsigned)(kt * 16 * XROW_B) + b_roff;
            ldsm_x4_t(bh, xhib + boff);
            ldsm_x4_t(bl, xlob + boff);
            unsigned ach = (((kt * 2 + a_cb) ^ li) << 4);
            #pragma unroll
            for (int mt = 0; mt < 6; ++mt) {
                unsigned ah[4], al[4];
                unsigned arow = (unsigned)(mt * 16 + a_row) * 128 + ach;
                ldsm_x4(ah, smem_base + SM_WHI + arow);
                ldsm_x4(al, smem_base + SM_WLO + arow);
                mma_bf16(acc[mt] + 0, ah, bh + 0);
                mma_bf16(acc[mt] + 4, ah, bh + 2);
                mma_bf16(acc[mt] + 0, ah, bl + 0);
                mma_bf16(acc[mt] + 4, ah, bl + 2);
                mma_bf16(acc[mt] + 0, al, bh + 0);
                mma_bf16(acc[mt] + 4, al, bh + 2);
            }
        }

        // ---- tanh on all fragments (paired rcp) ----
        #pragma unroll
        for (int mt = 0; mt < 6; ++mt)
            #pragma unroll
            for (int p = 0; p < 4; ++p)
                tanh_pair(acc[mt][2 * p], acc[mt][2 * p + 1]);

        unsigned mbal = __ballot_sync(0xffffffffu, lv >= 1.0f);
        float scl2 = rsqrtf((float)(__popc(mbal) + 1)) * 1.4426950408889634f;

        // ---- fold scl2 into Q, then build Q A-fragments ----
        #pragma unroll
        for (int p = 0; p < 8; ++p) { acc[0][p] *= scl2; acc[1][p] *= scl2; }

        unsigned qh0[4], ql0[4], qh1[4], ql1[4];
        split_pair(acc[0][0], acc[0][1], qh0[0], ql0[0]);
        split_pair(acc[0][2], acc[0][3], qh0[1], ql0[1]);
        split_pair(acc[0][4], acc[0][5], qh0[2], ql0[2]);
        split_pair(acc[0][6], acc[0][7], qh0[3], ql0[3]);
        split_pair(acc[1][0], acc[1][1], qh1[0], ql1[0]);
        split_pair(acc[1][2], acc[1][3], qh1[1], ql1[1]);
        split_pair(acc[1][4], acc[1][5], qh1[2], ql1[2]);
        split_pair(acc[1][6], acc[1][7], qh1[3], ql1[3]);

        // ---- K B-fragments straight from C fragments (layout identity) ----
        unsigned kbh[4][2], kbl[4][2];
        split_pair(acc[2][0], acc[2][1], kbh[0][0], kbl[0][0]);
        split_pair(acc[2][4], acc[2][5], kbh[0][1], kbl[0][1]);
        split_pair(acc[2][2], acc[2][3], kbh[1][0], kbl[1][0]);
        split_pair(acc[2][6], acc[2][7], kbh[1][1], kbl[1][1]);
        split_pair(acc[3][0], acc[3][1], kbh[2][0], kbl[2][0]);
        split_pair(acc[3][4], acc[3][5], kbh[2][1], kbl[2][1]);
        split_pair(acc[3][2], acc[3][3], kbh[3][0], kbl[3][0]);
        split_pair(acc[3][6], acc[3][7], kbh[3][1], kbl[3][1]);

        // ---- scores (pre-scaled) = (scl2*Qt) @ Kt^T ----
        float sc[2][16];
        #pragma unroll
        for (int m = 0; m < 2; ++m)
            #pragma unroll
            for (int p = 0; p < 16; ++p) sc[m][p] = 0.0f;
        #pragma unroll
        for (int nt = 0; nt < 4; ++nt) {
            mma_bf16(sc[0] + nt * 4, qh0, kbh[nt]);
            mma_bf16(sc[0] + nt * 4, qh0, kbl[nt]);
            mma_bf16(sc[0] + nt * 4, ql0, kbh[nt]);
            mma_bf16(sc[1] + nt * 4, qh1, kbh[nt]);
            mma_bf16(sc[1] + nt * 4, qh1, kbl[nt]);
            mma_bf16(sc[1] + nt * 4, ql1, kbh[nt]);
        }

        // ---- e = exp2(score) in place (scale pre-folded) ----
        #pragma unroll
        for (int m = 0; m < 2; ++m)
            #pragma unroll
            for (int p = 0; p < 16; ++p) sc[m][p] = ex2f(sc[m][p]);

        // ---- esum per row; reduce over quad ----
        float rA0 = 0.0f, rA1 = 0.0f, rB0 = 0.0f, rB1 = 0.0f;
        #pragma unroll
        for (int nt = 0; nt < 4; ++nt) {
            rA0 += sc[0][nt * 4 + 0] + sc[0][nt * 4 + 1];
            rA1 += sc[0][nt * 4 + 2] + sc[0][nt * 4 + 3];
            rB0 += sc[1][nt * 4 + 0] + sc[1][nt * 4 + 1];
            rB1 += sc[1][nt * 4 + 2] + sc[1][nt * 4 + 3];
        }
        ull u0 = pack2(rA0, rA1), u1 = pack2(rB0, rB1);
        u0 = add2(u0, __shfl_xor_sync(0xffffffffu, u0, 1));
        u0 = add2(u0, __shfl_xor_sync(0xffffffffu, u0, 2));
        u1 = add2(u1, __shfl_xor_sync(0xffffffffu, u1, 1));
        u1 = add2(u1, __shfl_xor_sync(0xffffffffu, u1, 2));
        float es0, es1, es2, es3;
        unpack2(u0, es0, es1); unpack2(u1, es2, es3);
        // batched reciprocals (2 rcp instead of 4)
        float r01 = rcpf(es0 * es1), r23 = rcpf(es2 * es3);
        float w0 = aoR0 * (r01 * es1);
        float w1 = aoR1 * (r01 * es0);
        float w2 = aoR2 * (r23 * es3);
        float w3 = aoR3 * (r23 * es2);

        // ---- g[s] = sum_r w[r] e[r][s]; reduce over g-lanes ----
        ull w00 = pack2(w0, w0), w11 = pack2(w1, w1);
        ull w22 = pack2(w2, w2), w33 = pack2(w3, w3);
        ull gp[4];
        #pragma unroll
        for (int nt = 0; nt < 4; ++nt) {
            ull a = 0ull;
            fma2(a, w00, pack2(sc[0][nt * 4 + 0], sc[0][nt * 4 + 1]));
            fma2(a, w11, pack2(sc[0][nt * 4 + 2], sc[0][nt * 4 + 3]));
            fma2(a, w22, pack2(sc[1][nt * 4 + 0], sc[1][nt * 4 + 1]));
            fma2(a, w33, pack2(sc[1][nt * 4 + 2], sc[1][nt * 4 + 3]));
            gp[nt] = a;
        }
        #pragma unroll
        for (int nt = 0; nt < 4; ++nt) {
            gp[nt] = add2(gp[nt], __shfl_xor_sync(0xffffffffu, gp[nt], 4));
            gp[nt] = add2(gp[nt], __shfl_xor_sync(0xffffffffu, gp[nt], 8));
            gp[nt] = add2(gp[nt], __shfl_xor_sync(0xffffffffu, gp[nt], 16));
        }

        // ---- align g[s] with V rows ----
        const int src  = lane >> 3;
        const int bsel = (lane >> 2) & 1;
        float gv[4];
        #pragma unroll
        for (int j = 0; j < 4; ++j) {
            ull gs = __shfl_sync(0xffffffffu, gp[j], src);
            float lo, hi; unpack2(gs, lo, hi);
            gv[j] = bsel ? hi : lo;
        }

        // ---- c[n] = sum_s g[s] V[s][n]; reduce over g-lanes ----
        ull g00 = pack2(gv[0], gv[0]), g11 = pack2(gv[1], gv[1]);
        ull g22 = pack2(gv[2], gv[2]), g33 = pack2(gv[3], gv[3]);
        ull cp01 = 0ull, cp23 = 0ull;
        fma2(cp01, g00, pack2(acc[4][0], acc[4][1]));
        fma2(cp01, g11, pack2(acc[4][2], acc[4][3]));
        fma2(cp01, g22, pack2(acc[5][0], acc[5][1]));
        fma2(cp01, g33, pack2(acc[5][2], acc[5][3]));
        fma2(cp23, g00, pack2(acc[4][4], acc[4][5]));
        fma2(cp23, g11, pack2(acc[4][6], acc[4][7]));
        fma2(cp23, g22, pack2(acc[5][4], acc[5][5]));
        fma2(cp23, g33, pack2(acc[5][6], acc[5][7]));
        cp01 = add2(cp01, __shfl_xor_sync(0xffffffffu, cp01, 4));
        cp01 = add2(cp01, __shfl_xor_sync(0xffffffffu, cp01, 8));
        cp01 = add2(cp01, __shfl_xor_sync(0xffffffffu, cp01, 16));
        cp23 = add2(cp23, __shfl_xor_sync(0xffffffffu, cp23, 4));
        cp23 = add2(cp23, __shfl_xor_sync(0xffffffffu, cp23, 8));
        cp23 = add2(cp23, __shfl_xor_sync(0xffffffffu, cp23, 16));
        float c0, c1, c2, c3;
        unpack2(cp01, c0, c1); unpack2(cp23, c2, c3);

        // ---- tanh^2 (paired rcp), rowsum (quad), Laplacian write ----
        tanh_pair(c0, c1);
        tanh_pair(c2, c3);
        float r20 = c0 * c0, r21 = c1 * c1, r22 = c2 * c2, r23v = c3 * c3;
        float rs = r20 + r21 + r22 + r23v;
        rs += __shfl_xor_sync(0xffffffffu, rs, 1);
        rs += __shfl_xor_sync(0xffffffffu, rs, 2);

        if (lane < 4) {
            int i  = b & 15;
            int n0 = 2 * lane;
            int n2 = 8 + 2 * lane;
            float* op = out + (size_t)b * 16;
            *(float2*)(op + n0) = make_float2(
                (n0     == i) ? rs : -r20,
                (n0 + 1 == i) ? rs : -r21);
            *(float2*)(op + n2) = make_float2(
                (n2     == i) ? rs : -r22,
                (n2 + 1 == i) ? rs : -r23v);
        }
        __syncwarp();
    }
}

extern "C" void kernel_launch(void* const* d_in, const int* in_sizes, int n_in,
                              void* d_out, int out_size) {
    const float* x  = (const float*)d_in[0];
    const float* L  = (const float*)d_in[1];
    const float* Aq = (const float*)d_in[2];
    const float* Ak = (const float*)d_in[3];
    const float* Av = (const float*)d_in[4];
    const float* Ao = (const float*)d_in[5];
    float* out = (float*)d_out;

    cudaFuncSetAttribute(att_mask_kernel,
                         cudaFuncAttributeMaxDynamicSharedMemorySize, SMEM_BYTES);
    att_mask_kernel<<<NCTAS, THREADS, SMEM_BYTES>>>(x, L, Aq, Ak, Av, Ao, out);
}

// round 12
// speedup vs baseline: 1.0834x; 1.0834x over previous
#include <cuda_runtime.h>
#include <cuda_bf16.h>
#include <cstdint>

// Att_mask R12: R10 proven skeleton (register-resident HMMA pipeline, 24 warps/SM)
// + scl2 folded into Q fragments pre-split (removes 32 score-path FMAs)
// + prefetch.global.L2 of next batch's x (consecutive batches per warp)
// tanh_pair REVERTED (R11 post-mortem: traded hidden MUFU for visible fma/alu).
// Grid back to NCTAS=2048 / ITERS=4 (R11's 1024/8 cost 2% occupancy).

typedef unsigned long long ull;

#define THREADS 256
#define WPB     8
#define NCTAS   2048
#define ITERS   4            // 2048 * 8 warps * 4 = 65536 batches

#define SM_WHI   0           // 96 rows x 128B bf16, chunk-swizzled
#define SM_WLO   12288
#define SM_WARP0 24576
#define PW_BYTES 6144        // per-warp: xhi 3072 | xlo 3072
#define SMEM_BYTES (SM_WARP0 + WPB * PW_BYTES + 128)

#define XROW_B   48          // x bf16 tile row stride (conflict-free LDSM.trans)
#define TANH_K   2.8853900817779268f   // 2*log2(e)

// ---------------- packed f32x2 helpers ----------------
__device__ __forceinline__ ull pack2(float lo, float hi) {
    ull r; asm("mov.b64 %0, {%1, %2};" : "=l"(r) : "f"(lo), "f"(hi)); return r;
}
__device__ __forceinline__ void unpack2(ull v, float& lo, float& hi) {
    asm("mov.b64 {%0, %1}, %2;" : "=f"(lo), "=f"(hi) : "l"(v));
}
__device__ __forceinline__ void fma2(ull& d, ull a, ull b) {
    asm("fma.rn.f32x2 %0, %1, %2, %0;" : "+l"(d) : "l"(a), "l"(b));
}
__device__ __forceinline__ ull add2(ull a, ull b) {
    ull r; asm("add.rn.f32x2 %0, %1, %2;" : "=l"(r) : "l"(a), "l"(b)); return r;
}
__device__ __forceinline__ float ex2f(float x) {
    float r; asm("ex2.approx.f32 %0, %1;" : "=f"(r) : "f"(x)); return r;
}
__device__ __forceinline__ float fast_tanh(float x) {      // 1-2/(e^2x+1), ~1e-6
    float e = ex2f(TANH_K * x);
    return 1.0f - __fdividef(2.0f, e + 1.0f);
}

// ---------------- smem / mma helpers ----------------
__device__ __forceinline__ unsigned smem_u32(const void* p) {
    unsigned a;
    asm("{ .reg .u64 t; cvta.to.shared.u64 t, %1; cvt.u32.u64 %0, t; }" : "=r"(a) : "l"(p));
    return a;
}
__device__ __forceinline__ unsigned cvtpack2(float lo, float hi) {
    unsigned r; asm("cvt.rn.bf16x2.f32 %0, %1, %2;" : "=r"(r) : "f"(hi), "f"(lo)); return r;
}
__device__ __forceinline__ void split_pair(float a, float b, unsigned& hi, unsigned& lo) {
    hi = cvtpack2(a, b);
    float ha = __uint_as_float(hi << 16);
    float hb = __uint_as_float(hi & 0xffff0000u);
    lo = cvtpack2(a - ha, b - hb);
}
__device__ __forceinline__ void ldsm_x4(unsigned r[4], unsigned addr) {
    asm volatile("ldmatrix.sync.aligned.m8n8.x4.shared.b16 {%0,%1,%2,%3}, [%4];"
                 : "=r"(r[0]), "=r"(r[1]), "=r"(r[2]), "=r"(r[3]) : "r"(addr));
}
__device__ __forceinline__ void ldsm_x4_t(unsigned r[4], unsigned addr) {
    asm volatile("ldmatrix.sync.aligned.m8n8.x4.trans.shared.b16 {%0,%1,%2,%3}, [%4];"
                 : "=r"(r[0]), "=r"(r[1]), "=r"(r[2]), "=r"(r[3]) : "r"(addr));
}
__device__ __forceinline__ void mma_bf16(float* c, const unsigned* a, const unsigned* b) {
    asm volatile("mma.sync.aligned.m16n8k16.row.col.f32.bf16.bf16.f32 "
                 "{%0,%1,%2,%3}, {%4,%5,%6,%7}, {%8,%9}, {%0,%1,%2,%3};"
                 : "+f"(c[0]), "+f"(c[1]), "+f"(c[2]), "+f"(c[3])
                 : "r"(a[0]), "r"(a[1]), "r"(a[2]), "r"(a[3]), "r"(b[0]), "r"(b[1]));
}
__device__ __forceinline__ void sts_v2(unsigned addr, unsigned a, unsigned b) {
    asm volatile("st.shared.v2.b32 [%0], {%1, %2};" :: "r"(addr), "r"(a), "r"(b));
}

__global__ void __launch_bounds__(THREADS, 3) att_mask_kernel(
    const float* __restrict__ x, const float* __restrict__ L,
    const float* __restrict__ Aq, const float* __restrict__ Ak,
    const float* __restrict__ Av, const float* __restrict__ Ao,
    float* __restrict__ out)
{
    extern __shared__ char smem[];
    const int tid  = threadIdx.x;
    const int warp = tid >> 5;
    const int lane = tid & 31;
    const int g    = lane >> 2;
    const unsigned smem_base = smem_u32(smem);

    // ---- stage W split-bf16, chunk-swizzled [96 rows][128B] (proven) ----
    for (int idx = tid; idx < 6144; idx += THREADS) {
        int row = idx >> 6, d = idx & 63;
        float val = (row < 32) ? Aq[row * 64 + d]
                  : (row < 64) ? Ak[(row - 32) * 64 + d]
                               : Av[(row - 64) * 64 + d];
        __nv_bfloat16 h = __float2bfloat16(val);
        __nv_bfloat16 l = __float2bfloat16(val - __bfloat162float(h));
        int off = row * 128 + (((d >> 3) ^ (row & 7)) << 4) + (d & 7) * 2;
        *(__nv_bfloat16*)(smem + SM_WHI + off) = h;
        *(__nv_bfloat16*)(smem + SM_WLO + off) = l;
    }
    float aoR0 = __ldg(Ao + g);
    float aoR1 = __ldg(Ao + g + 8);
    float aoR2 = __ldg(Ao + g + 16);
    float aoR3 = __ldg(Ao + g + 24);
    __syncthreads();

    const unsigned xhib = smem_base + SM_WARP0 + warp * PW_BYTES;
    const unsigned xlob = xhib + 3072;

    // ldmatrix lane addressing (proven)
    const int lm = lane >> 3;
    const int li = lane & 7;
    const unsigned a_row  = ((lm & 1) << 3) + li;
    const unsigned a_cb   = (unsigned)(lm >> 1);
    const unsigned b_roff = (((lm & 1) << 3) + li) * XROW_B + ((lm >> 1) << 4);

    const int gw = blockIdx.x * WPB + warp;

    for (int it = 0; it < ITERS; ++it) {
        const int b = gw * ITERS + it;    // consecutive batches per warp

        // ---- load x coalesced + L ----
        const float4* xg4 = (const float4*)(x + (size_t)b * 1024);
        float4 xv[8];
        #pragma unroll
        for (int j = 0; j < 8; ++j) xv[j] = xg4[j * 32 + lane];
        float lv = (lane < 16) ? __ldg(L + (size_t)b * 256 + lane) : 0.0f;

        __syncwarp();

        // ---- convert x to bf16 hi/lo tiles [d=64][n=16], rows 48B ----
        #pragma unroll
        for (int j = 0; j < 8; ++j) {
            float4 v = xv[j];
            unsigned h01 = cvtpack2(v.x, v.y);
            unsigned h23 = cvtpack2(v.z, v.w);
            float f0 = __uint_as_float(h01 << 16);
            float f1 = __uint_as_float(h01 & 0xffff0000u);
            float f2 = __uint_as_float(h23 << 16);
            float f3 = __uint_as_float(h23 & 0xffff0000u);
            unsigned l01 = cvtpack2(v.x - f0, v.y - f1);
            unsigned l23 = cvtpack2(v.z - f2, v.w - f3);
            unsigned off = (unsigned)((8 * j + (lane >> 2)) * XROW_B + (lane & 3) * 8);
            sts_v2(xhib + off, h01, h23);
            sts_v2(xlob + off, l01, l23);
        }
        // ---- L2 prefetch of next iteration's x (4KB via lane*128) ----
        if (it + 1 < ITERS) {
            const char* nx = (const char*)(x + (size_t)(b + 1) * 1024);
            asm volatile("prefetch.global.L2 [%0];" :: "l"(nx + lane * 128));
        }
        __syncwarp();

        // ---- projection: 3 terms x (6 mt x 2 nt x 4 kt) mma.sync ----
        float acc[6][8];
        #pragma unroll
        for (int mt = 0; mt < 6; ++mt)
            #pragma unroll
            for (int p = 0; p < 8; ++p) acc[mt][p] = 0.0f;

        #pragma unroll
        for (int kt = 0; kt < 4; ++kt) {
            unsigned bh[4], bl[4];
            unsigned boff = (unsigned)(kt * 16 * XROW_B) + b_roff;
            ldsm_x4_t(bh, xhib + boff);
            ldsm_x4_t(bl, xlob + boff);
            unsigned ach = (((kt * 2 + a_cb) ^ li) << 4);
            #pragma unroll
            for (int mt = 0; mt < 6; ++mt) {
                unsigned ah[4], al[4];
                unsigned arow = (unsigned)(mt * 16 + a_row) * 128 + ach;
                ldsm_x4(ah, smem_base + SM_WHI + arow);
                ldsm_x4(al, smem_base + SM_WLO + arow);
                mma_bf16(acc[mt] + 0, ah, bh + 0);
                mma_bf16(acc[mt] + 4, ah, bh + 2);
                mma_bf16(acc[mt] + 0, ah, bl + 0);
                mma_bf16(acc[mt] + 4, ah, bl + 2);
                mma_bf16(acc[mt] + 0, al, bh + 0);
                mma_bf16(acc[mt] + 4, al, bh + 2);
            }
        }

        // ---- tanh on all fragments ----
        #pragma unroll
        for (int mt = 0; mt < 6; ++mt)
            #pragma unroll
            for (int p = 0; p < 8; ++p) acc[mt][p] = fast_tanh(acc[mt][p]);

        unsigned mbal = __ballot_sync(0xffffffffu, lv >= 1.0f);
        float scl2 = rsqrtf((float)(__popc(mbal) + 1)) * 1.4426950408889634f;

        // ---- fold scl2 into Q, then build Q A-fragments ----
        #pragma unroll
        for (int p = 0; p < 8; ++p) { acc[0][p] *= scl2; acc[1][p] *= scl2; }

        unsigned qh0[4], ql0[4], qh1[4], ql1[4];
        split_pair(acc[0][0], acc[0][1], qh0[0], ql0[0]);
        split_pair(acc[0][2], acc[0][3], qh0[1], ql0[1]);
        split_pair(acc[0][4], acc[0][5], qh0[2], ql0[2]);
        split_pair(acc[0][6], acc[0][7], qh0[3], ql0[3]);
        split_pair(acc[1][0], acc[1][1], qh1[0], ql1[0]);
        split_pair(acc[1][2], acc[1][3], qh1[1], ql1[1]);
        split_pair(acc[1][4], acc[1][5], qh1[2], ql1[2]);
        split_pair(acc[1][6], acc[1][7], qh1[3], ql1[3]);

        // ---- K B-fragments straight from C fragments (layout identity) ----
        unsigned kbh[4][2], kbl[4][2];
        split_pair(acc[2][0], acc[2][1], kbh[0][0], kbl[0][0]);
        split_pair(acc[2][4], acc[2][5], kbh[0][1], kbl[0][1]);
        split_pair(acc[2][2], acc[2][3], kbh[1][0], kbl[1][0]);
        split_pair(acc[2][6], acc[2][7], kbh[1][1], kbl[1][1]);
        split_pair(acc[3][0], acc[3][1], kbh[2][0], kbl[2][0]);
        split_pair(acc[3][4], acc[3][5], kbh[2][1], kbl[2][1]);
        split_pair(acc[3][2], acc[3][3], kbh[3][0], kbl[3][0]);
        split_pair(acc[3][6], acc[3][7], kbh[3][1], kbl[3][1]);

        // ---- scores (pre-scaled) = (scl2*Qt) @ Kt^T ----
        float sc[2][16];
        #pragma unroll
        for (int m = 0; m < 2; ++m)
            #pragma unroll
            for (int p = 0; p < 16; ++p) sc[m][p] = 0.0f;
        #pragma unroll
        for (int nt = 0; nt < 4; ++nt) {
            mma_bf16(sc[0] + nt * 4, qh0, kbh[nt]);
            mma_bf16(sc[0] + nt * 4, qh0, kbl[nt]);
            mma_bf16(sc[0] + nt * 4, ql0, kbh[nt]);
            mma_bf16(sc[1] + nt * 4, qh1, kbh[nt]);
            mma_bf16(sc[1] + nt * 4, qh1, kbl[nt]);
            mma_bf16(sc[1] + nt * 4, ql1, kbh[nt]);
        }

        // ---- e = exp2(score) in place (scale pre-folded) ----
        #pragma unroll
        for (int m = 0; m < 2; ++m)
            #pragma unroll
            for (int p = 0; p < 16; ++p) sc[m][p] = ex2f(sc[m][p]);

        // ---- esum per row; reduce over quad ----
        float rA0 = 0.0f, rA1 = 0.0f, rB0 = 0.0f, rB1 = 0.0f;
        #pragma unroll
        for (int nt = 0; nt < 4; ++nt) {
            rA0 += sc[0][nt * 4 + 0] + sc[0][nt * 4 + 1];
            rA1 += sc[0][nt * 4 + 2] + sc[0][nt * 4 + 3];
            rB0 += sc[1][nt * 4 + 0] + sc[1][nt * 4 + 1];
            rB1 += sc[1][nt * 4 + 2] + sc[1][nt * 4 + 3];
        }
        ull u0 = pack2(rA0, rA1), u1 = pack2(rB0, rB1);
        u0 = add2(u0, __shfl_xor_sync(0xffffffffu, u0, 1));
        u0 = add2(u0, __shfl_xor_sync(0xffffffffu, u0, 2));
        u1 = add2(u1, __shfl_xor_sync(0xffffffffu, u1, 1));
        u1 = add2(u1, __shfl_xor_sync(0xffffffffu, u1, 2));
        float es0, es1, es2, es3;
        unpack2(u0, es0, es1); unpack2(u1, es2, es3);
        float w0 = aoR0 * __fdividef(1.0f, es0);
        float w1 = aoR1 * __fdividef(1.0f, es1);
        float w2 = aoR2 * __fdividef(1.0f, es2);
        float w3 = aoR3 * __fdividef(1.0f, es3);

        // ---- g[s] = sum_r w[r] e[r][s]; reduce over g-lanes ----
        ull w00 = pack2(w0, w0), w11 = pack2(w1, w1);
        ull w22 = pack2(w2, w2), w33 = pack2(w3, w3);
        ull gp[4];
        #pragma unroll
        for (int nt = 0; nt < 4; ++nt) {
            ull a = 0ull;
            fma2(a, w00, pack2(sc[0][nt * 4 + 0], sc[0][nt * 4 + 1]));
            fma2(a, w11, pack2(sc[0][nt * 4 + 2], sc[0][nt * 4 + 3]));
            fma2(a, w22, pack2(sc[1][nt * 4 + 0], sc[1][nt * 4 + 1]));
            fma2(a, w33, pack2(sc[1][nt * 4 + 2], sc[1][nt * 4 + 3]));
            gp[nt] = a;
        }
        #pragma unroll
        for (int nt = 0; nt < 4; ++nt) {
            gp[nt] = add2(gp[nt], __shfl_xor_sync(0xffffffffu, gp[nt], 4));
            gp[nt] = add2(gp[nt], __shfl_xor_sync(0xffffffffu, gp[nt], 8));
            gp[nt] = add2(gp[nt], __shfl_xor_sync(0xffffffffu, gp[nt], 16));
        }

        // ---- align g[s] with V rows ----
        const int src  = lane >> 3;
        const int bsel = (lane >> 2) & 1;
        float gv[4];
        #pragma unroll
        for (int j = 0; j < 4; ++j) {
            ull gs = __shfl_sync(0xffffffffu, gp[j], src);
            float lo, hi; unpack2(gs, lo, hi);
            gv[j] = bsel ? hi : lo;
        }

        // ---- c[n] = sum_s g[s] V[s][n]; reduce over g-lanes ----
        ull g00 = pack2(gv[0], gv[0]), g11 = pack2(gv[1], gv[1]);
        ull g22 = pack2(gv[2], gv[2]), g33 = pack2(gv[3], gv[3]);
        ull cp01 = 0ull, cp23 = 0ull;
        fma2(cp01, g00, pack2(acc[4][0], acc[4][1]));
        fma2(cp01, g11, pack2(acc[4][2], acc[4][3]));
        fma2(cp01, g22, pack2(acc[5][0], acc[5][1]));
        fma2(cp01, g33, pack2(acc[5][2], acc[5][3]));
        fma2(cp23, g00, pack2(acc[4][4], acc[4][5]));
        fma2(cp23, g11, pack2(acc[4][6], acc[4][7]));
        fma2(cp23, g22, pack2(acc[5][4], acc[5][5]));
        fma2(cp23, g33, pack2(acc[5][6], acc[5][7]));
        cp01 = add2(cp01, __shfl_xor_sync(0xffffffffu, cp01, 4));
        cp01 = add2(cp01, __shfl_xor_sync(0xffffffffu, cp01, 8));
        cp01 = add2(cp01, __shfl_xor_sync(0xffffffffu, cp01, 16));
        cp23 = add2(cp23, __shfl_xor_sync(0xffffffffu, cp23, 4));
        cp23 = add2(cp23, __shfl_xor_sync(0xffffffffu, cp23, 8));
        cp23 = add2(cp23, __shfl_xor_sync(0xffffffffu, cp23, 16));
        float c0, c1, c2, c3;
        unpack2(cp01, c0, c1); unpack2(cp23, c2, c3);

        // ---- tanh^2, rowsum (quad), Laplacian write (lanes 0-3) ----
        float t0 = fast_tanh(c0), t1 = fast_tanh(c1);
        float t2 = fast_tanh(c2), t3 = fast_tanh(c3);
        float r20 = t0 * t0, r21 = t1 * t1, r22 = t2 * t2, r23 = t3 * t3;
        float rs = r20 + r21 + r22 + r23;
        rs += __shfl_xor_sync(0xffffffffu, rs, 1);
        rs += __shfl_xor_sync(0xffffffffu, rs, 2);

        if (lane < 4) {
            int i  = b & 15;
            int n0 = 2 * lane;
            int n2 = 8 + 2 * lane;
            float* op = out + (size_t)b * 16;
            *(float2*)(op + n0) = make_float2(
                (n0     == i) ? rs : -r20,
                (n0 + 1 == i) ? rs : -r21);
            *(float2*)(op + n2) = make_float2(
                (n2     == i) ? rs : -r22,
                (n2 + 1 == i) ? rs : -r23);
        }
        __syncwarp();
    }
}

extern "C" void kernel_launch(void* const* d_in, const int* in_sizes, int n_in,
                              void* d_out, int out_size) {
    const float* x  = (const float*)d_in[0];
    const float* L  = (const float*)d_in[1];
    const float* Aq = (const float*)d_in[2];
    const float* Ak = (const float*)d_in[3];
    const float* Av = (const float*)d_in[4];
    const float* Ao = (const float*)d_in[5];
    float* out = (float*)d_out;

    cudaFuncSetAttribute(att_mask_kernel,
                         cudaFuncAttributeMaxDynamicSharedMemorySize, SMEM_BYTES);
    att_mask_kernel<<<NCTAS, THREADS, SMEM_BYTES>>>(x, L, Aq, Ak, Av, Ao, out);
}